// round 3
// baseline (speedup 1.0000x reference)
#include <cuda_runtime.h>
#include <cuda_bf16.h>
#include <cstdint>

// ---------------------------------------------------------------------------
// Scratch (device globals — no allocations allowed)
// ---------------------------------------------------------------------------
// g_Y : normalized input, NHWC, tf32-rounded fp32. [32][56][56][256]
// g_Wt: transformed weights, [9*256][256] (k-major, oc contiguous), tf32-rounded
__device__ float g_Y[32 * 56 * 56 * 256];
__device__ float g_Wt[9 * 256 * 256];

// ---------------------------------------------------------------------------
// Kernel 1: Golay scale + FWHT(256) + RMSNorm  -> g_Y (NHWC)
// One block = 32 consecutive pixels of one image. 256 threads (8 warps).
// Each warp transforms 4 pixels; channel vector split 8 regs x 32 lanes.
// ---------------------------------------------------------------------------
__global__ __launch_bounds__(256) void wht_kernel(const float* __restrict__ x,
                                                  const float* __restrict__ rmsw) {
    __shared__ float s[256][33];
    const int p0   = blockIdx.x * 32;   // pixel base within image (0..3135)
    const int n    = blockIdx.y;
    const int t    = threadIdx.x;
    const int lane = t & 31;
    const int warp = t >> 5;

    // Coalesced load: warp w loads channels [w*32, w*32+32), 32 pixels each.
    const float* xb = x + (size_t)n * 256 * 3136 + p0 + lane;
#pragma unroll 8
    for (int it = 0; it < 32; ++it) {
        int ch = warp * 32 + it;
        float v = xb[(size_t)ch * 3136];
        // Golay/Rudin-Shapiro sign: (-1)^popc(ch & (ch>>1))
        float gs = (__popc(ch & (ch >> 1)) & 1) ? -1.0f : 1.0f;
        s[ch][lane] = v * gs;
    }
    __syncthreads();

    float* Yb = g_Y + ((size_t)(n * 3136 + p0)) * 256;

    for (int j = 0; j < 4; ++j) {
        int pl = warp * 4 + j;          // pixel handled by this warp
        float v[8];
#pragma unroll
        for (int i = 0; i < 8; ++i) v[i] = s[i * 32 + lane][pl];  // ch = i*32+lane

        // Butterflies on channel bits 5..7 (register index bits)
#pragma unroll
        for (int b = 0; b < 3; ++b) {
            int m = 1 << b;
#pragma unroll
            for (int i = 0; i < 8; ++i) {
                if (!(i & m)) {
                    float lo = v[i], hi = v[i | m];
                    v[i]     = lo + hi;
                    v[i | m] = lo - hi;
                }
            }
        }
        // Butterflies on channel bits 0..4 (lane bits) via shfl_xor
#pragma unroll
        for (int b = 0; b < 5; ++b) {
            int m = 1 << b;
#pragma unroll
            for (int i = 0; i < 8; ++i) {
                float o = __shfl_xor_sync(0xffffffffu, v[i], m);
                v[i] = (lane & m) ? (o - v[i]) : (v[i] + o);
            }
        }
        // RMS over 256 channels
        float ss = 0.0f;
#pragma unroll
        for (int i = 0; i < 8; ++i) ss += v[i] * v[i];
#pragma unroll
        for (int off = 16; off; off >>= 1) ss += __shfl_xor_sync(0xffffffffu, ss, off);
        float sc = rsqrtf(ss * (1.0f / 256.0f) + 1e-5f);

#pragma unroll
        for (int i = 0; i < 8; ++i) {
            float val = v[i] * sc * rmsw[i * 32 + lane];
            uint32_t u;
            asm("cvt.rna.tf32.f32 %0, %1;" : "=r"(u) : "f"(val));  // unbiased tf32 round
            Yb[(size_t)pl * 256 + i * 32 + lane] = __uint_as_float(u);
        }
    }
}

// ---------------------------------------------------------------------------
// Kernel 2: W[oc][ic][kh][kw] -> Wt[(khw*256+ic)][oc], tf32-rounded
// ---------------------------------------------------------------------------
__global__ __launch_bounds__(256) void wt_kernel(const float* __restrict__ W) {
    int oc  = threadIdx.x;
    int row = blockIdx.x;            // khw*256 + ic
    int khw = row >> 8;
    int ic  = row & 255;
    float v = W[(size_t)oc * 2304 + ic * 9 + khw];
    uint32_t u;
    asm("cvt.rna.tf32.f32 %0, %1;" : "=r"(u) : "f"(v));
    g_Wt[(size_t)row * 256 + oc] = __uint_as_float(u);
}

// ---------------------------------------------------------------------------
// Kernel 3: implicit-GEMM 3x3 conv via mma.sync tf32.
// Block tile: M=128 pixels (spatial 8x16), N=256 oc, K-chunk=32, 72 chunks.
// 8 warps as 2(m) x 4(n); warp tile 64x64; mma m16n8k8: 4 m-tiles x 8 n-tiles.
// 2-stage cp.async pipeline. Halo via cp.async zero-fill.
// ---------------------------------------------------------------------------
#define AS_STAGE (128 * 36)   // A smem, m-major, pad 36 (conflict-free frags)
#define BS_STAGE (32 * 264)   // B smem, k-major, pad 264 (conflict-free frags)

__global__ __launch_bounds__(256, 1) void conv_kernel(const float* __restrict__ bias,
                                                      float* __restrict__ out) {
    extern __shared__ float smem[];
    float* As = smem;                 // [2][128][36]
    float* Bs = smem + 2 * AS_STAGE;  // [2][32][264]

    const int wtile = blockIdx.x;         // 0..3 -> w0 = 0,16,32,48
    const int h0    = blockIdx.y * 8;     // 0..48
    const int n     = blockIdx.z;
    const int w0    = wtile * 16;
    const int t     = threadIdx.x;
    const int lane  = t & 31;
    const int warp  = t >> 5;
    const int warp_m = warp >> 2;         // 0..1
    const int warp_n = warp & 3;          // 0..3
    const int g  = lane >> 2;
    const int t4 = lane & 3;

    const float* Yb = g_Y + (size_t)n * (3136 * 256);

    float c[4][8][4];
#pragma unroll
    for (int mt = 0; mt < 4; ++mt)
#pragma unroll
        for (int nt = 0; nt < 8; ++nt)
#pragma unroll
            for (int r = 0; r < 4; ++r) c[mt][nt][r] = 0.0f;

    uint32_t s_as = (uint32_t)__cvta_generic_to_shared(As);
    uint32_t s_bs = (uint32_t)__cvta_generic_to_shared(Bs);

    auto issue = [&](int q, int st) {
        int khw   = q >> 3;               // 0..8
        int icblk = (q & 7) << 5;         // 0..224
        int kh = khw / 3;
        int kw = khw - kh * 3;
        // A tile: 128 pixels x 32 ic = 1024 float4, 4 per thread
#pragma unroll
        for (int j = 0; j < 4; ++j) {
            int f4 = j * 256 + t;
            int m  = f4 >> 3, q4 = f4 & 7;
            int r  = m >> 4,  cc = m & 15;
            int ph = h0 + r + kh - 1;
            int pw = w0 + cc + kw - 1;
            bool v = ((unsigned)ph < 56u) && ((unsigned)pw < 56u);
            const float* gp = v ? (Yb + ((size_t)(ph * 56 + pw)) * 256 + icblk + q4 * 4) : Yb;
            uint32_t sa = s_as + (uint32_t)((st * AS_STAGE + m * 36 + q4 * 4) * 4);
            int sz = v ? 16 : 0;
            asm volatile("cp.async.cg.shared.global [%0], [%1], 16, %2;\n"
                         :: "r"(sa), "l"(gp), "r"(sz));
        }
        // B tile: 32 k x 256 oc = 2048 float4, 8 per thread
        const float* Wb = g_Wt + ((size_t)(khw * 256 + icblk)) * 256;
#pragma unroll
        for (int j = 0; j < 8; ++j) {
            int f4 = j * 256 + t;
            int k  = f4 >> 6, n4 = f4 & 63;
            const float* gp = Wb + (size_t)k * 256 + n4 * 4;
            uint32_t sa = s_bs + (uint32_t)((st * BS_STAGE + k * 264 + n4 * 4) * 4);
            asm volatile("cp.async.cg.shared.global [%0], [%1], 16;\n"
                         :: "r"(sa), "l"(gp));
        }
        asm volatile("cp.async.commit_group;\n");
    };

    issue(0, 0);

    for (int q = 0; q < 72; ++q) {
        int st = q & 1;
        if (q + 1 < 72) {
            issue(q + 1, st ^ 1);
            asm volatile("cp.async.wait_group 1;\n");
        } else {
            asm volatile("cp.async.wait_group 0;\n");
        }
        __syncthreads();

        const float* A = As + st * AS_STAGE;
        const float* B = Bs + st * BS_STAGE;

#pragma unroll
        for (int ks = 0; ks < 4; ++ks) {
            uint32_t a[4][4], bf[8][2];
#pragma unroll
            for (int mt = 0; mt < 4; ++mt) {
                int mb = warp_m * 64 + mt * 16;
                const float* Ar  = A + (mb + g) * 36 + ks * 8 + t4;
                const float* Ar2 = A + (mb + g + 8) * 36 + ks * 8 + t4;
                a[mt][0] = __float_as_uint(Ar[0]);
                a[mt][1] = __float_as_uint(Ar2[0]);
                a[mt][2] = __float_as_uint(Ar[4]);
                a[mt][3] = __float_as_uint(Ar2[4]);
            }
#pragma unroll
            for (int nt = 0; nt < 8; ++nt) {
                int nb = warp_n * 64 + nt * 8 + g;
                bf[nt][0] = __float_as_uint(B[(ks * 8 + t4) * 264 + nb]);
                bf[nt][1] = __float_as_uint(B[(ks * 8 + t4 + 4) * 264 + nb]);
            }
#pragma unroll
            for (int mt = 0; mt < 4; ++mt)
#pragma unroll
                for (int nt = 0; nt < 8; ++nt) {
                    asm volatile(
                        "mma.sync.aligned.m16n8k8.row.col.f32.tf32.tf32.f32 "
                        "{%0,%1,%2,%3}, {%4,%5,%6,%7}, {%8,%9}, {%0,%1,%2,%3};\n"
                        : "+f"(c[mt][nt][0]), "+f"(c[mt][nt][1]),
                          "+f"(c[mt][nt][2]), "+f"(c[mt][nt][3])
                        : "r"(a[mt][0]), "r"(a[mt][1]), "r"(a[mt][2]), "r"(a[mt][3]),
                          "r"(bf[nt][0]), "r"(bf[nt][1]));
                }
        }
        __syncthreads();
    }

    // Epilogue: c0:(g,2t4) c1:(g,2t4+1) c2:(g+8,2t4) c3:(g+8,2t4+1)
    float* ob = out + (size_t)n * (256 * 3136);
#pragma unroll
    for (int nt = 0; nt < 8; ++nt) {
        int oc = warp_n * 64 + nt * 8 + t4 * 2;
        float b0 = bias[oc], b1 = bias[oc + 1];
#pragma unroll
        for (int mt = 0; mt < 4; ++mt) {
            int h  = h0 + warp_m * 4 + mt;
            int wA = w0 + g;
            int wB = w0 + g + 8;
            float* o0 = ob + ((size_t)oc * 56 + h) * 56;
            float* o1 = o0 + 3136;   // oc+1
            if (wA < 56) {
                o0[wA] = c[mt][nt][0] + b0;
                o1[wA] = c[mt][nt][1] + b1;
            }
            if (wB < 56) {
                o0[wB] = c[mt][nt][2] + b0;
                o1[wB] = c[mt][nt][3] + b1;
            }
        }
    }
}

// ---------------------------------------------------------------------------
// Launcher (graph-capturable: kernel launches only)
// ---------------------------------------------------------------------------
extern "C" void kernel_launch(void* const* d_in, const int* in_sizes, int n_in,
                              void* d_out, int out_size) {
    const float* x    = (const float*)d_in[0];
    const float* W    = (const float*)d_in[1];
    const float* b    = (const float*)d_in[2];
    const float* rmsw = (const float*)d_in[3];
    float* out = (float*)d_out;

    wht_kernel<<<dim3(98, 32), 256>>>(x, rmsw);
    wt_kernel<<<2304, 256>>>(W);

    const int smem_bytes = (2 * AS_STAGE + 2 * BS_STAGE) * 4;  // 104448
    cudaFuncSetAttribute(conv_kernel, cudaFuncAttributeMaxDynamicSharedMemorySize,
                         smem_bytes);
    conv_kernel<<<dim3(4, 7, 32), 256, smem_bytes>>>(b, out);
}

// round 5
// speedup vs baseline: 1.7504x; 1.7504x over previous
#include <cuda_runtime.h>
#include <cuda_fp16.h>
#include <cstdint>

// ---------------------------------------------------------------------------
// Scratch (device globals — no allocations allowed)
// ---------------------------------------------------------------------------
// g_Yh : normalized input, NHWC, fp16. [32*56*56][256]
// g_Wth: weights as B matrix, fp16, [oc][k] with k = khw*256+ic
__device__ __half g_Yh[32 * 56 * 56 * 256];
__device__ __half g_Wth[256 * 2304];

// ---------------------------------------------------------------------------
// Kernel 1: Golay scale + FWHT(256) + RMSNorm -> g_Yh (NHWC, fp16)
// ---------------------------------------------------------------------------
__global__ __launch_bounds__(256) void wht_kernel(const float* __restrict__ x,
                                                  const float* __restrict__ rmsw) {
    __shared__ float s[256][33];
    const int p0   = blockIdx.x * 32;
    const int n    = blockIdx.y;
    const int t    = threadIdx.x;
    const int lane = t & 31;
    const int warp = t >> 5;

    const float* xb = x + (size_t)n * 256 * 3136 + p0 + lane;
#pragma unroll 8
    for (int it = 0; it < 32; ++it) {
        int ch = warp * 32 + it;
        float v = xb[(size_t)ch * 3136];
        float gs = (__popc(ch & (ch >> 1)) & 1) ? -1.0f : 1.0f;  // Rudin-Shapiro
        s[ch][lane] = v * gs;
    }
    __syncthreads();

    __half* Yb = g_Yh + ((size_t)(n * 3136 + p0)) * 256;

    for (int j = 0; j < 4; ++j) {
        int pl = warp * 4 + j;
        float v[8];
#pragma unroll
        for (int i = 0; i < 8; ++i) v[i] = s[i * 32 + lane][pl];
#pragma unroll
        for (int b = 0; b < 3; ++b) {
            int m = 1 << b;
#pragma unroll
            for (int i = 0; i < 8; ++i)
                if (!(i & m)) {
                    float lo = v[i], hi = v[i | m];
                    v[i] = lo + hi;
                    v[i | m] = lo - hi;
                }
        }
#pragma unroll
        for (int b = 0; b < 5; ++b) {
            int m = 1 << b;
#pragma unroll
            for (int i = 0; i < 8; ++i) {
                float o = __shfl_xor_sync(0xffffffffu, v[i], m);
                v[i] = (lane & m) ? (o - v[i]) : (v[i] + o);
            }
        }
        float ss = 0.0f;
#pragma unroll
        for (int i = 0; i < 8; ++i) ss += v[i] * v[i];
#pragma unroll
        for (int off = 16; off; off >>= 1) ss += __shfl_xor_sync(0xffffffffu, ss, off);
        float sc = rsqrtf(ss * (1.0f / 256.0f) + 1e-5f);
#pragma unroll
        for (int i = 0; i < 8; ++i) {
            float val = v[i] * sc * rmsw[i * 32 + lane];
            Yb[(size_t)pl * 256 + i * 32 + lane] = __float2half_rn(val);
        }
    }
}

// ---------------------------------------------------------------------------
// Kernel 2: W[oc][ic][kh][kw] -> g_Wth[oc][khw*256+ic], fp16
// ---------------------------------------------------------------------------
__global__ __launch_bounds__(256) void wt_kernel(const float* __restrict__ W) {
    int b   = blockIdx.x;       // oc*9 + khw
    int oc  = b / 9;
    int khw = b - oc * 9;
    int ic  = threadIdx.x;
    float v = W[(size_t)oc * 2304 + ic * 9 + khw];
    g_Wth[(size_t)oc * 2304 + khw * 256 + ic] = __float2half_rn(v);
}

// ---------------------------------------------------------------------------
// Kernel 3: implicit-GEMM conv, fp16 mma.sync.m16n8k16, fp32 accum.
// CTA: M=128 linear pixels, N=256 oc, K=2304 in 36 chunks of 64.
// 8 warps as 2(m) x 4(n); warp tile 64x64 -> 4 m-tiles x 8 n-tiles x 4 ksteps.
// 3-stage cp.async ring. Smem rows padded to 72 halves (conflict-free frags).
// ---------------------------------------------------------------------------
#define A_HALFS     (128 * 72)
#define B_HALFS     (256 * 72)
#define STAGE_HALFS (A_HALFS + B_HALFS)          // 27648 halves = 55296 B
#define CONV_SMEM   (3 * STAGE_HALFS * 2)        // 165888 B

__global__ __launch_bounds__(256, 1) void conv_kernel(const float* __restrict__ bias,
                                                      float* __restrict__ out) {
    extern __shared__ __half sm[];
    const int t      = threadIdx.x;
    const int lane   = t & 31;
    const int warp   = t >> 5;
    const int warp_m = warp >> 2;    // 0..1
    const int warp_n = warp & 3;     // 0..3
    const int g      = lane >> 2;    // 0..7
    const int t4     = lane & 3;     // 0..3

    // --- cp.async geometry (per thread, constant across chunks) ---
    const int rbase = t >> 3;        // 0..31
    const int u     = t & 7;         // 16B unit in 128B row-chunk
    int PH[4], PW[4], NB[4];
#pragma unroll
    for (int j = 0; j < 4; ++j) {
        int P = blockIdx.x * 128 + rbase + 32 * j;
        int n = P / 3136;
        int p = P - n * 3136;
        PH[j] = p / 56;
        PW[j] = p - PH[j] * 56;
        NB[j] = n * 3136;
    }

    float c[4][8][4];
#pragma unroll
    for (int mt = 0; mt < 4; ++mt)
#pragma unroll
        for (int nt = 0; nt < 8; ++nt)
#pragma unroll
            for (int r = 0; r < 4; ++r) c[mt][nt][r] = 0.0f;

    uint32_t sbase = (uint32_t)__cvta_generic_to_shared(sm);

    auto issue = [&](int q, int st) {
        int khw   = q >> 2;              // k chunk = [64q, 64q+64): khw = q/4
        int icblk = (q & 3) << 6;        // ic block of 64
        int kh = khw / 3;
        int kw = khw - kh * 3;
        uint32_t abase = sbase + (uint32_t)(st * STAGE_HALFS * 2);
        uint32_t bbase = abase + A_HALFS * 2;
        // A: 128 rows x 8 units of 16B (halo rows zero-filled)
#pragma unroll
        for (int j = 0; j < 4; ++j) {
            int ph = PH[j] + kh - 1;
            int pw = PW[j] + kw - 1;
            bool v = ((unsigned)ph < 56u) && ((unsigned)pw < 56u);
            const __half* gp = v ? (g_Yh + ((size_t)(NB[j] + ph * 56 + pw)) * 256 + icblk + u * 8)
                                 : g_Yh;
            uint32_t sa = abase + (uint32_t)((rbase + 32 * j) * 144 + u * 16);
            int sz = v ? 16 : 0;
            asm volatile("cp.async.cg.shared.global [%0], [%1], 16, %2;\n"
                         :: "r"(sa), "l"(gp), "r"(sz));
        }
        // B: 256 oc rows x 8 units of 16B
        const __half* Wb = g_Wth + q * 64 + u * 8;
#pragma unroll
        for (int j = 0; j < 8; ++j) {
            int oc = rbase + 32 * j;
            const __half* gp = Wb + (size_t)oc * 2304;
            uint32_t sa = bbase + (uint32_t)(oc * 144 + u * 16);
            asm volatile("cp.async.cg.shared.global [%0], [%1], 16;\n"
                         :: "r"(sa), "l"(gp));
        }
        asm volatile("cp.async.commit_group;\n");
    };

    issue(0, 0);
    issue(1, 1);
    issue(2, 2);

    for (int q = 0; q < 36; ++q) {
        int st = q - (q / 3) * 3;
        if (q <= 33)      asm volatile("cp.async.wait_group 2;\n" ::: "memory");
        else if (q == 34) asm volatile("cp.async.wait_group 1;\n" ::: "memory");
        else              asm volatile("cp.async.wait_group 0;\n" ::: "memory");
        __syncthreads();

        const __half* As = sm + st * STAGE_HALFS;
        const __half* Bs = As + A_HALFS;

#pragma unroll
        for (int ks = 0; ks < 4; ++ks) {
            int k0 = ks * 16;
            uint32_t a[4][4], b[8][2];
#pragma unroll
            for (int mt = 0; mt < 4; ++mt) {
                int bm = warp_m * 64 + mt * 16;
                const __half* r0 = As + (bm + g) * 72 + k0 + 2 * t4;
                const __half* r1 = As + (bm + g + 8) * 72 + k0 + 2 * t4;
                a[mt][0] = *(const uint32_t*)(r0);
                a[mt][1] = *(const uint32_t*)(r1);
                a[mt][2] = *(const uint32_t*)(r0 + 8);
                a[mt][3] = *(const uint32_t*)(r1 + 8);
            }
#pragma unroll
            for (int nt = 0; nt < 8; ++nt) {
                const __half* br = Bs + (warp_n * 64 + nt * 8 + g) * 72 + k0 + 2 * t4;
                b[nt][0] = *(const uint32_t*)(br);
                b[nt][1] = *(const uint32_t*)(br + 8);
            }
#pragma unroll
            for (int mt = 0; mt < 4; ++mt)
#pragma unroll
                for (int nt = 0; nt < 8; ++nt) {
                    asm volatile(
                        "mma.sync.aligned.m16n8k16.row.col.f32.f16.f16.f32 "
                        "{%0,%1,%2,%3}, {%4,%5,%6,%7}, {%8,%9}, {%0,%1,%2,%3};\n"
                        : "+f"(c[mt][nt][0]), "+f"(c[mt][nt][1]),
                          "+f"(c[mt][nt][2]), "+f"(c[mt][nt][3])
                        : "r"(a[mt][0]), "r"(a[mt][1]), "r"(a[mt][2]), "r"(a[mt][3]),
                          "r"(b[nt][0]), "r"(b[nt][1]));
                }
        }
        __syncthreads();
        if (q + 3 < 36) issue(q + 3, st);
    }

    // --- epilogue ---
    // c0:(m=g, oc=2t4) c1:(g, 2t4+1) c2:(g+8, 2t4) c3:(g+8, 2t4+1)
#pragma unroll
    for (int mt = 0; mt < 4; ++mt) {
        int P0 = blockIdx.x * 128 + warp_m * 64 + mt * 16 + g;
        int P1 = P0 + 8;
        int n0 = P0 / 3136, n1 = P1 / 3136;
        size_t o0 = (size_t)n0 * (256 * 3136) + (P0 - n0 * 3136);
        size_t o1 = (size_t)n1 * (256 * 3136) + (P1 - n1 * 3136);
#pragma unroll
        for (int nt = 0; nt < 8; ++nt) {
            int oc = warp_n * 64 + nt * 8 + 2 * t4;
            float b0 = __ldg(bias + oc), b1 = __ldg(bias + oc + 1);
            out[o0 + (size_t)oc * 3136]       = c[mt][nt][0] + b0;
            out[o0 + (size_t)(oc + 1) * 3136] = c[mt][nt][1] + b1;
            out[o1 + (size_t)oc * 3136]       = c[mt][nt][2] + b0;
            out[o1 + (size_t)(oc + 1) * 3136] = c[mt][nt][3] + b1;
        }
    }
}

// ---------------------------------------------------------------------------
// Launcher (graph-capturable: kernel launches only)
// ---------------------------------------------------------------------------
extern "C" void kernel_launch(void* const* d_in, const int* in_sizes, int n_in,
                              void* d_out, int out_size) {
    const float* x    = (const float*)d_in[0];
    const float* W    = (const float*)d_in[1];
    const float* b    = (const float*)d_in[2];
    const float* rmsw = (const float*)d_in[3];
    float* out = (float*)d_out;

    wht_kernel<<<dim3(98, 32), 256>>>(x, rmsw);
    wt_kernel<<<2304, 256>>>(W);

    cudaFuncSetAttribute(conv_kernel, cudaFuncAttributeMaxDynamicSharedMemorySize,
                         CONV_SMEM);
    conv_kernel<<<784, 256, CONV_SMEM>>>(b, out);
}

// round 6
// speedup vs baseline: 1.7827x; 1.0185x over previous
#include <cuda_runtime.h>
#include <cuda_fp16.h>
#include <cstdint>

// ---------------------------------------------------------------------------
// Scratch (device globals — no allocations allowed)
// ---------------------------------------------------------------------------
__device__ __half g_Yh[32 * 56 * 56 * 256];   // NHWC fp16 normalized input
__device__ __half g_Wth[256 * 2304];          // [oc][khw*256+ic] fp16

// ---------------------------------------------------------------------------
// Kernel 1: Golay scale + FWHT(256) + RMSNorm -> g_Yh (NHWC, fp16)
// ---------------------------------------------------------------------------
__global__ __launch_bounds__(256) void wht_kernel(const float* __restrict__ x,
                                                  const float* __restrict__ rmsw) {
    __shared__ float s[256][33];
    const int p0   = blockIdx.x * 32;
    const int n    = blockIdx.y;
    const int t    = threadIdx.x;
    const int lane = t & 31;
    const int warp = t >> 5;

    const float* xb = x + (size_t)n * 256 * 3136 + p0 + lane;
#pragma unroll 8
    for (int it = 0; it < 32; ++it) {
        int ch = warp * 32 + it;
        float v = xb[(size_t)ch * 3136];
        float gs = (__popc(ch & (ch >> 1)) & 1) ? -1.0f : 1.0f;  // Rudin-Shapiro
        s[ch][lane] = v * gs;
    }
    __syncthreads();

    __half* Yb = g_Yh + ((size_t)(n * 3136 + p0)) * 256;

    for (int j = 0; j < 4; ++j) {
        int pl = warp * 4 + j;
        float v[8];
#pragma unroll
        for (int i = 0; i < 8; ++i) v[i] = s[i * 32 + lane][pl];
#pragma unroll
        for (int b = 0; b < 3; ++b) {
            int m = 1 << b;
#pragma unroll
            for (int i = 0; i < 8; ++i)
                if (!(i & m)) {
                    float lo = v[i], hi = v[i | m];
                    v[i] = lo + hi;
                    v[i | m] = lo - hi;
                }
        }
#pragma unroll
        for (int b = 0; b < 5; ++b) {
            int m = 1 << b;
#pragma unroll
            for (int i = 0; i < 8; ++i) {
                float o = __shfl_xor_sync(0xffffffffu, v[i], m);
                v[i] = (lane & m) ? (o - v[i]) : (v[i] + o);
            }
        }
        float ss = 0.0f;
#pragma unroll
        for (int i = 0; i < 8; ++i) ss += v[i] * v[i];
#pragma unroll
        for (int off = 16; off; off >>= 1) ss += __shfl_xor_sync(0xffffffffu, ss, off);
        float sc = rsqrtf(ss * (1.0f / 256.0f) + 1e-5f);
#pragma unroll
        for (int i = 0; i < 8; ++i) {
            float val = v[i] * sc * rmsw[i * 32 + lane];
            Yb[(size_t)pl * 256 + i * 32 + lane] = __float2half_rn(val);
        }
    }
}

// ---------------------------------------------------------------------------
// Kernel 2: W[oc][ic][kh][kw] -> g_Wth[oc][khw*256+ic], fp16
// ---------------------------------------------------------------------------
__global__ __launch_bounds__(256) void wt_kernel(const float* __restrict__ W) {
    int b   = blockIdx.x;       // oc*9 + khw
    int oc  = b / 9;
    int khw = b - oc * 9;
    int ic  = threadIdx.x;
    float v = W[(size_t)oc * 2304 + ic * 9 + khw];
    g_Wth[(size_t)oc * 2304 + khw * 256 + ic] = __float2half_rn(v);
}

// ---------------------------------------------------------------------------
// Kernel 3: implicit-GEMM conv, fp16 mma.sync.m16n8k16, fp32 accum.
// M=128 linear pixels, N=256, K=2304 in 36 chunks of 64.
// ldmatrix.x4 fragment loads, register-double-buffered across 4 ksteps.
// 4-stage cp.async ring, ONE __syncthreads per chunk (issue-before-compute).
// Smem rows padded to 72 halves (144B) -> conflict-free LDSM.
// ---------------------------------------------------------------------------
#define A_BYTES     (128 * 144)              // 18432
#define B_BYTES     (256 * 144)              // 36864
#define STAGE_BYTES (A_BYTES + B_BYTES)      // 55296
#define CONV_SMEM   (4 * STAGE_BYTES)        // 221184

#define LDSM4(r0, r1, r2, r3, addr)                                            \
    asm volatile("ldmatrix.sync.aligned.m8n8.x4.shared.b16 {%0,%1,%2,%3}, [%4];" \
                 : "=r"(r0), "=r"(r1), "=r"(r2), "=r"(r3) : "r"(addr))

__global__ __launch_bounds__(256, 1) void conv_kernel(const float* __restrict__ bias,
                                                      float* __restrict__ out) {
    extern __shared__ __half sm[];
    const int t      = threadIdx.x;
    const int lane   = t & 31;
    const int warp   = t >> 5;
    const int warp_m = warp >> 2;    // 0..1
    const int warp_n = warp & 3;     // 0..3
    const int g      = lane >> 2;
    const int t4     = lane & 3;

    uint32_t sbase = (uint32_t)__cvta_generic_to_shared(sm);

    // --- cp.async geometry (per thread, constant across chunks) ---
    const int rbase = t >> 3;        // 0..31
    const int u     = t & 7;         // 16B unit in 128B row-chunk
    int PH[4], PW[4], NB[4];
#pragma unroll
    for (int j = 0; j < 4; ++j) {
        int P = blockIdx.x * 128 + rbase + 32 * j;
        int n = P / 3136;
        int p = P - n * 3136;
        PH[j] = p / 56;
        PW[j] = p - PH[j] * 56;
        NB[j] = n * 3136;
    }

    // --- ldmatrix per-lane offsets (bytes within stage) ---
    // A frag sub-order: bit3 of lane -> row+8, bit4 -> col+8
    // B frag sub-order: bit3 of lane -> col+8, bit4 -> row+8
    const int arow = (lane & 7) + (((lane >> 3) & 1) << 3);
    const int acol = (lane >> 4) << 3;
    const int brow = (lane & 7) + ((lane >> 4) << 3);
    const int bcol = ((lane >> 3) & 1) << 3;
    uint32_t aoff[4], boff[4];
#pragma unroll
    for (int mt = 0; mt < 4; ++mt)
        aoff[mt] = (uint32_t)(((warp_m * 64 + mt * 16 + arow) * 72 + acol) * 2);
#pragma unroll
    for (int j = 0; j < 4; ++j)
        boff[j] = (uint32_t)(A_BYTES + ((warp_n * 64 + j * 16 + brow) * 72 + bcol) * 2);

    float c[4][8][4];
#pragma unroll
    for (int mt = 0; mt < 4; ++mt)
#pragma unroll
        for (int nt = 0; nt < 8; ++nt)
#pragma unroll
            for (int r = 0; r < 4; ++r) c[mt][nt][r] = 0.0f;

    auto issue = [&](int q, int st) {
        int khw   = q >> 2;
        int icblk = (q & 3) << 6;
        int kh = khw / 3;
        int kw = khw - kh * 3;
        uint32_t abase = sbase + (uint32_t)(st * STAGE_BYTES);
        uint32_t bbase = abase + A_BYTES;
#pragma unroll
        for (int j = 0; j < 4; ++j) {
            int ph = PH[j] + kh - 1;
            int pw = PW[j] + kw - 1;
            bool v = ((unsigned)ph < 56u) && ((unsigned)pw < 56u);
            const __half* gp = v ? (g_Yh + ((size_t)(NB[j] + ph * 56 + pw)) * 256 + icblk + u * 8)
                                 : g_Yh;
            uint32_t sa = abase + (uint32_t)((rbase + 32 * j) * 144 + u * 16);
            int sz = v ? 16 : 0;
            asm volatile("cp.async.cg.shared.global [%0], [%1], 16, %2;\n"
                         :: "r"(sa), "l"(gp), "r"(sz));
        }
        const __half* Wb = g_Wth + q * 64 + u * 8;
#pragma unroll
        for (int j = 0; j < 8; ++j) {
            int oc = rbase + 32 * j;
            const __half* gp = Wb + (size_t)oc * 2304;
            uint32_t sa = bbase + (uint32_t)(oc * 144 + u * 16);
            asm volatile("cp.async.cg.shared.global [%0], [%1], 16;\n"
                         :: "r"(sa), "l"(gp));
        }
        asm volatile("cp.async.commit_group;\n");
    };

    issue(0, 0);
    issue(1, 1);
    issue(2, 2);

    for (int q = 0; q < 36; ++q) {
        int st = q & 3;
        if (q <= 33)      asm volatile("cp.async.wait_group 2;\n" ::: "memory");
        else if (q == 34) asm volatile("cp.async.wait_group 1;\n" ::: "memory");
        else              asm volatile("cp.async.wait_group 0;\n" ::: "memory");
        __syncthreads();
        // All warps finished compute(q-1) => stage (q+3)&3 == (q-1)&3 is free.
        if (q + 3 < 36) issue(q + 3, (q + 3) & 3);

        uint32_t abase = sbase + (uint32_t)(st * STAGE_BYTES);

        uint32_t a0[16], b0[16], a1[16], b1[16];
#pragma unroll
        for (int mt = 0; mt < 4; ++mt)
            LDSM4(a0[mt * 4], a0[mt * 4 + 1], a0[mt * 4 + 2], a0[mt * 4 + 3],
                  abase + aoff[mt]);
#pragma unroll
        for (int j = 0; j < 4; ++j)
            LDSM4(b0[j * 4], b0[j * 4 + 1], b0[j * 4 + 2], b0[j * 4 + 3],
                  abase + boff[j]);

#pragma unroll
        for (int ks = 0; ks < 4; ++ks) {
            uint32_t* ac = (ks & 1) ? a1 : a0;
            uint32_t* bc = (ks & 1) ? b1 : b0;
            if (ks < 3) {
                uint32_t* an = (ks & 1) ? a0 : a1;
                uint32_t* bn = (ks & 1) ? b0 : b1;
                uint32_t ko = (uint32_t)((ks + 1) * 32);
#pragma unroll
                for (int mt = 0; mt < 4; ++mt)
                    LDSM4(an[mt * 4], an[mt * 4 + 1], an[mt * 4 + 2], an[mt * 4 + 3],
                          abase + aoff[mt] + ko);
#pragma unroll
                for (int j = 0; j < 4; ++j)
                    LDSM4(bn[j * 4], bn[j * 4 + 1], bn[j * 4 + 2], bn[j * 4 + 3],
                          abase + boff[j] + ko);
            }
#pragma unroll
            for (int mt = 0; mt < 4; ++mt)
#pragma unroll
                for (int nt = 0; nt < 8; ++nt) {
                    int bj = (nt >> 1) * 4 + (nt & 1) * 2;
                    asm volatile(
                        "mma.sync.aligned.m16n8k16.row.col.f32.f16.f16.f32 "
                        "{%0,%1,%2,%3}, {%4,%5,%6,%7}, {%8,%9}, {%0,%1,%2,%3};\n"
                        : "+f"(c[mt][nt][0]), "+f"(c[mt][nt][1]),
                          "+f"(c[mt][nt][2]), "+f"(c[mt][nt][3])
                        : "r"(ac[mt * 4]), "r"(ac[mt * 4 + 1]),
                          "r"(ac[mt * 4 + 2]), "r"(ac[mt * 4 + 3]),
                          "r"(bc[bj]), "r"(bc[bj + 1]));
                }
        }
    }

    // --- epilogue ---
#pragma unroll
    for (int mt = 0; mt < 4; ++mt) {
        int P0 = blockIdx.x * 128 + warp_m * 64 + mt * 16 + g;
        int P1 = P0 + 8;
        int n0 = P0 / 3136, n1 = P1 / 3136;
        size_t o0 = (size_t)n0 * (256 * 3136) + (P0 - n0 * 3136);
        size_t o1 = (size_t)n1 * (256 * 3136) + (P1 - n1 * 3136);
#pragma unroll
        for (int nt = 0; nt < 8; ++nt) {
            int oc = warp_n * 64 + nt * 8 + 2 * t4;
            float b0 = __ldg(bias + oc), b1 = __ldg(bias + oc + 1);
            out[o0 + (size_t)oc * 3136]       = c[mt][nt][0] + b0;
            out[o0 + (size_t)(oc + 1) * 3136] = c[mt][nt][1] + b1;
            out[o1 + (size_t)oc * 3136]       = c[mt][nt][2] + b0;
            out[o1 + (size_t)(oc + 1) * 3136] = c[mt][nt][3] + b1;
        }
    }
}

// ---------------------------------------------------------------------------
// Launcher (graph-capturable: kernel launches only)
// ---------------------------------------------------------------------------
extern "C" void kernel_launch(void* const* d_in, const int* in_sizes, int n_in,
                              void* d_out, int out_size) {
    const float* x    = (const float*)d_in[0];
    const float* W    = (const float*)d_in[1];
    const float* b    = (const float*)d_in[2];
    const float* rmsw = (const float*)d_in[3];
    float* out = (float*)d_out;

    wht_kernel<<<dim3(98, 32), 256>>>(x, rmsw);
    wt_kernel<<<2304, 256>>>(W);

    cudaFuncSetAttribute(conv_kernel, cudaFuncAttributeMaxDynamicSharedMemorySize,
                         CONV_SMEM);
    conv_kernel<<<784, 256, CONV_SMEM>>>(b, out);
}

// round 7
// speedup vs baseline: 2.2112x; 1.2404x over previous
#include <cuda_runtime.h>
#include <cuda_fp16.h>
#include <cstdint>

// ---------------------------------------------------------------------------
// Scratch (device globals — no allocations allowed)
// ---------------------------------------------------------------------------
__device__ __half g_Yh[32 * 56 * 56 * 256];          // NHWC fp16 normalized input
__device__ __half g_V[16 * 25088 * 256];             // Winograd input transform [r][tile][ic]
__device__ __half g_U[16 * 256 * 256];               // Winograd weights [r][oc][ic]

// ---------------------------------------------------------------------------
// Kernel 1: Golay scale + FWHT(256) + RMSNorm -> g_Yh (NHWC, fp16) [unchanged]
// ---------------------------------------------------------------------------
__global__ __launch_bounds__(256) void wht_kernel(const float* __restrict__ x,
                                                  const float* __restrict__ rmsw) {
    __shared__ float s[256][33];
    const int p0   = blockIdx.x * 32;
    const int n    = blockIdx.y;
    const int t    = threadIdx.x;
    const int lane = t & 31;
    const int warp = t >> 5;

    const float* xb = x + (size_t)n * 256 * 3136 + p0 + lane;
#pragma unroll 8
    for (int it = 0; it < 32; ++it) {
        int ch = warp * 32 + it;
        float v = xb[(size_t)ch * 3136];
        float gs = (__popc(ch & (ch >> 1)) & 1) ? -1.0f : 1.0f;  // Rudin-Shapiro
        s[ch][lane] = v * gs;
    }
    __syncthreads();

    __half* Yb = g_Yh + ((size_t)(n * 3136 + p0)) * 256;

    for (int j = 0; j < 4; ++j) {
        int pl = warp * 4 + j;
        float v[8];
#pragma unroll
        for (int i = 0; i < 8; ++i) v[i] = s[i * 32 + lane][pl];
#pragma unroll
        for (int b = 0; b < 3; ++b) {
            int m = 1 << b;
#pragma unroll
            for (int i = 0; i < 8; ++i)
                if (!(i & m)) {
                    float lo = v[i], hi = v[i | m];
                    v[i] = lo + hi;
                    v[i | m] = lo - hi;
                }
        }
#pragma unroll
        for (int b = 0; b < 5; ++b) {
            int m = 1 << b;
#pragma unroll
            for (int i = 0; i < 8; ++i) {
                float o = __shfl_xor_sync(0xffffffffu, v[i], m);
                v[i] = (lane & m) ? (o - v[i]) : (v[i] + o);
            }
        }
        float ss = 0.0f;
#pragma unroll
        for (int i = 0; i < 8; ++i) ss += v[i] * v[i];
#pragma unroll
        for (int off = 16; off; off >>= 1) ss += __shfl_xor_sync(0xffffffffu, ss, off);
        float sc = rsqrtf(ss * (1.0f / 256.0f) + 1e-5f);
#pragma unroll
        for (int i = 0; i < 8; ++i) {
            float val = v[i] * sc * rmsw[i * 32 + lane];
            Yb[(size_t)pl * 256 + i * 32 + lane] = __float2half_rn(val);
        }
    }
}

// ---------------------------------------------------------------------------
// Kernel 2: Winograd input transform  V = B^T d B  (fp32 math, fp16 store)
// Block: 256 thr = 4 tiles x 64 threads; each thread does 4 channels.
// B^T = [[1,0,-1,0],[0,1,1,0],[0,-1,1,0],[0,1,0,-1]]
// ---------------------------------------------------------------------------
__global__ __launch_bounds__(256) void wino_in(void) {
    const int t  = threadIdx.x;
    const int tg = t >> 6;          // tile within block
    const int lt = t & 63;          // 4-channel group
    const int T  = blockIdx.x * 4 + tg;
    const int n   = T / 784;
    const int rem = T - n * 784;
    const int ty  = rem / 28;
    const int tx  = rem - ty * 28;

    uint2 dly[16];
#pragma unroll
    for (int dy = 0; dy < 4; ++dy)
#pragma unroll
        for (int dx = 0; dx < 4; ++dx) {
            int py = 2 * ty - 1 + dy;
            int px = 2 * tx - 1 + dx;
            bool valid = ((unsigned)py < 56u) && ((unsigned)px < 56u);
            if (valid)
                dly[dy * 4 + dx] = *(const uint2*)(g_Yh +
                    ((size_t)(n * 3136 + py * 56 + px)) * 256 + lt * 4);
            else
                dly[dy * 4 + dx] = make_uint2(0u, 0u);
        }

    __half2 vpack[2][16];
#pragma unroll
    for (int cp = 0; cp < 2; ++cp) {
        float da[16], db[16];
#pragma unroll
        for (int i = 0; i < 16; ++i) {
            uint32_t w = cp ? dly[i].y : dly[i].x;
            __half2 h2 = *(__half2*)&w;
            da[i] = __low2float(h2);
            db[i] = __high2float(h2);
        }
#pragma unroll
        for (int cc = 0; cc < 2; ++cc) {
            float* d = cc ? db : da;
            float tt[16];
#pragma unroll
            for (int xx = 0; xx < 4; ++xx) {
                tt[0 * 4 + xx] = d[0 * 4 + xx] - d[2 * 4 + xx];
                tt[1 * 4 + xx] = d[1 * 4 + xx] + d[2 * 4 + xx];
                tt[2 * 4 + xx] = d[2 * 4 + xx] - d[1 * 4 + xx];
                tt[3 * 4 + xx] = d[1 * 4 + xx] - d[3 * 4 + xx];
            }
            float V[16];
#pragma unroll
            for (int u = 0; u < 4; ++u) {
                V[u * 4 + 0] = tt[u * 4 + 0] - tt[u * 4 + 2];
                V[u * 4 + 1] = tt[u * 4 + 1] + tt[u * 4 + 2];
                V[u * 4 + 2] = tt[u * 4 + 2] - tt[u * 4 + 1];
                V[u * 4 + 3] = tt[u * 4 + 1] - tt[u * 4 + 3];
            }
#pragma unroll
            for (int r = 0; r < 16; ++r) {
                __half hv = __float2half_rn(V[r]);
                if (cc == 0) vpack[cp][r] = __halves2half2(hv, hv);
                else         vpack[cp][r] = __halves2half2(__low2half(vpack[cp][r]), hv);
            }
        }
    }
#pragma unroll
    for (int r = 0; r < 16; ++r) {
        uint2 w;
        w.x = *(uint32_t*)&vpack[0][r];
        w.y = *(uint32_t*)&vpack[1][r];
        *(uint2*)(g_V + ((size_t)r * 25088 + T) * 256 + lt * 4) = w;
    }
}

// ---------------------------------------------------------------------------
// Kernel 3: Winograd weight transform  U = G g G^T  (fp32 math, fp16 store)
// G = [[1,0,0],[.5,.5,.5],[.5,-.5,.5],[0,0,1]]
// ---------------------------------------------------------------------------
__global__ __launch_bounds__(256) void wino_wt(const float* __restrict__ W) {
    int oc = blockIdx.x;
    int ic = threadIdx.x;
    const float* g = W + ((size_t)oc * 256 + ic) * 9;
    float gg[9];
#pragma unroll
    for (int i = 0; i < 9; ++i) gg[i] = g[i];
    float tt[12];
#pragma unroll
    for (int j = 0; j < 3; ++j) {
        tt[0 * 3 + j] = gg[0 * 3 + j];
        tt[1 * 3 + j] = 0.5f * (gg[0 * 3 + j] + gg[1 * 3 + j] + gg[2 * 3 + j]);
        tt[2 * 3 + j] = 0.5f * (gg[0 * 3 + j] - gg[1 * 3 + j] + gg[2 * 3 + j]);
        tt[3 * 3 + j] = gg[2 * 3 + j];
    }
#pragma unroll
    for (int u = 0; u < 4; ++u) {
        float U0 = tt[u * 3 + 0];
        float U1 = 0.5f * (tt[u * 3 + 0] + tt[u * 3 + 1] + tt[u * 3 + 2]);
        float U2 = 0.5f * (tt[u * 3 + 0] - tt[u * 3 + 1] + tt[u * 3 + 2]);
        float U3 = tt[u * 3 + 2];
        g_U[(size_t)(u * 4 + 0) * 65536 + oc * 256 + ic] = __float2half_rn(U0);
        g_U[(size_t)(u * 4 + 1) * 65536 + oc * 256 + ic] = __float2half_rn(U1);
        g_U[(size_t)(u * 4 + 2) * 65536 + oc * 256 + ic] = __float2half_rn(U2);
        g_U[(size_t)(u * 4 + 3) * 65536 + oc * 256 + ic] = __float2half_rn(U3);
    }
}

// ---------------------------------------------------------------------------
// Kernel 4: 16 fused GEMMs M_r = V_r * U_r^T + output transform Y = A^T M A.
// CTA: 64 tiles x 64 oc. 8 warps = 4(m) x 2(n); warp tile 16 tiles x 32 oc.
// Chunk = (r, kc): K=256 per r in 4 chunks of 64. 64 chunks total.
// 4-stage cp.async ring, one __syncthreads per chunk. Rows padded to 144B.
// A^T = [[1,1,1,0],[0,1,-1,-1]]
// ---------------------------------------------------------------------------
#define WA_BYTES   (64 * 144)                // 9216
#define WSTAGE     (2 * WA_BYTES)            // 18432
#define WG_SMEM    (4 * WSTAGE)              // 73728

#define LDSM4(r0, r1, r2, r3, addr)                                            \
    asm volatile("ldmatrix.sync.aligned.m8n8.x4.shared.b16 {%0,%1,%2,%3}, [%4];" \
                 : "=r"(r0), "=r"(r1), "=r"(r2), "=r"(r3) : "r"(addr))

__global__ __launch_bounds__(256, 2) void wino_gemm(const float* __restrict__ bias,
                                                    float* __restrict__ out) {
    extern __shared__ __half sm[];
    const int t      = threadIdx.x;
    const int lane   = t & 31;
    const int warp   = t >> 5;
    const int warp_m = warp >> 1;   // 0..3
    const int warp_n = warp & 1;    // 0..1
    const int g      = lane >> 2;
    const int t4     = lane & 3;

    const int OB = blockIdx.x * 64;   // oc block
    const int TB = blockIdx.y * 64;   // tile block

    uint32_t sbase = (uint32_t)__cvta_generic_to_shared(sm);

    // cp.async geometry: 2 A units + 2 B units per thread
    const int row0 = t >> 3;          // 0..31
    const int u0   = t & 7;

    // ldmatrix lane offsets (verified layout from round 6)
    const int arow = (lane & 7) + (((lane >> 3) & 1) << 3);
    const int acol = (lane >> 4) << 3;
    const int brow = (lane & 7) + ((lane >> 4) << 3);
    const int bcol = ((lane >> 3) & 1) << 3;
    const uint32_t aoff = (uint32_t)(((warp_m * 16 + arow) * 72 + acol) * 2);
    uint32_t boff[2];
#pragma unroll
    for (int j = 0; j < 2; ++j)
        boff[j] = (uint32_t)(WA_BYTES + ((warp_n * 32 + j * 16 + brow) * 72 + bcol) * 2);

    float acc[4][16];
#pragma unroll
    for (int p = 0; p < 4; ++p)
#pragma unroll
        for (int e = 0; e < 16; ++e) acc[p][e] = 0.0f;
    float M[16];

    auto issue = [&](int q, int st) {
        int r  = q >> 2;
        int kc = q & 3;
        uint32_t abase = sbase + (uint32_t)(st * WSTAGE);
        const __half* Vb = g_V + ((size_t)r * 25088 + TB) * 256 + kc * 64;
        const __half* Ub = g_U + ((size_t)r * 256 + OB) * 256 + kc * 64;
#pragma unroll
        for (int j = 0; j < 2; ++j) {
            int row = row0 + j * 32;
            const __half* gp = Vb + (size_t)row * 256 + u0 * 8;
            uint32_t sa = abase + (uint32_t)(row * 144 + u0 * 16);
            asm volatile("cp.async.cg.shared.global [%0], [%1], 16;\n"
                         :: "r"(sa), "l"(gp));
        }
#pragma unroll
        for (int j = 0; j < 2; ++j) {
            int row = row0 + j * 32;
            const __half* gp = Ub + (size_t)row * 256 + u0 * 8;
            uint32_t sa = abase + (uint32_t)(WA_BYTES + row * 144 + u0 * 16);
            asm volatile("cp.async.cg.shared.global [%0], [%1], 16;\n"
                         :: "r"(sa), "l"(gp));
        }
        asm volatile("cp.async.commit_group;\n");
    };

    issue(0, 0);
    issue(1, 1);
    issue(2, 2);

    for (int q = 0; q < 64; ++q) {
        int st = q & 3;
        if (q < 62)       asm volatile("cp.async.wait_group 2;\n" ::: "memory");
        else if (q == 62) asm volatile("cp.async.wait_group 1;\n" ::: "memory");
        else              asm volatile("cp.async.wait_group 0;\n" ::: "memory");
        __syncthreads();
        if (q + 3 < 64) issue(q + 3, (q + 3) & 3);

        uint32_t abase = sbase + (uint32_t)(st * WSTAGE);

        if ((q & 3) == 0) {
#pragma unroll
            for (int e = 0; e < 16; ++e) M[e] = 0.0f;
        }

        uint32_t a0[4], a1[4], b0[8], b1[8];
        LDSM4(a0[0], a0[1], a0[2], a0[3], abase + aoff);
        LDSM4(b0[0], b0[1], b0[2], b0[3], abase + boff[0]);
        LDSM4(b0[4], b0[5], b0[6], b0[7], abase + boff[1]);

#pragma unroll
        for (int ks = 0; ks < 4; ++ks) {
            uint32_t* ac = (ks & 1) ? a1 : a0;
            uint32_t* bc = (ks & 1) ? b1 : b0;
            if (ks < 3) {
                uint32_t* an = (ks & 1) ? a0 : a1;
                uint32_t* bn = (ks & 1) ? b0 : b1;
                uint32_t ko = (uint32_t)((ks + 1) * 32);
                LDSM4(an[0], an[1], an[2], an[3], abase + aoff + ko);
                LDSM4(bn[0], bn[1], bn[2], bn[3], abase + boff[0] + ko);
                LDSM4(bn[4], bn[5], bn[6], bn[7], abase + boff[1] + ko);
            }
#pragma unroll
            for (int nt = 0; nt < 4; ++nt) {
                int bj = (nt >> 1) * 4 + (nt & 1) * 2;
                asm volatile(
                    "mma.sync.aligned.m16n8k16.row.col.f32.f16.f16.f32 "
                    "{%0,%1,%2,%3}, {%4,%5,%6,%7}, {%8,%9}, {%0,%1,%2,%3};\n"
                    : "+f"(M[nt * 4 + 0]), "+f"(M[nt * 4 + 1]),
                      "+f"(M[nt * 4 + 2]), "+f"(M[nt * 4 + 3])
                    : "r"(ac[0]), "r"(ac[1]), "r"(ac[2]), "r"(ac[3]),
                      "r"(bc[bj]), "r"(bc[bj + 1]));
            }
        }

        if ((q & 3) == 3) {
            int r = q >> 2;
            int uu = r >> 2, vv = r & 3;
            const float A0[4] = {1.0f, 1.0f, 1.0f, 0.0f};
            const float A1[4] = {0.0f, 1.0f, -1.0f, -1.0f};
            float c00 = A0[uu] * A0[vv];
            float c01 = A0[uu] * A1[vv];
            float c10 = A1[uu] * A0[vv];
            float c11 = A1[uu] * A1[vv];
#pragma unroll
            for (int e = 0; e < 16; ++e) {
                acc[0][e] += c00 * M[e];
                acc[1][e] += c01 * M[e];
                acc[2][e] += c10 * M[e];
                acc[3][e] += c11 * M[e];
            }
        }
    }

    // --- epilogue: acc[p= i*2+j][nt*4 + {0,1,2,3}] ---
    // reg 0:(tile g,   oc 2t4) 1:(g, 2t4+1) 2:(tile g+8, 2t4) 3:(g+8, 2t4+1)
    int T0 = TB + warp_m * 16 + g;
    int T1 = T0 + 8;
    int n0 = T0 / 784, r0 = T0 - n0 * 784;
    int n1 = T1 / 784, r1 = T1 - n1 * 784;
    int ty0 = r0 / 28, tx0 = r0 - ty0 * 28;
    int ty1 = r1 / 28, tx1 = r1 - ty1 * 28;
    size_t base0 = (size_t)n0 * (256 * 3136) + (2 * ty0) * 56 + 2 * tx0;
    size_t base1 = (size_t)n1 * (256 * 3136) + (2 * ty1) * 56 + 2 * tx1;

#pragma unroll
    for (int nt = 0; nt < 4; ++nt) {
        int oc = OB + warp_n * 32 + nt * 8 + 2 * t4;
        float bv0 = __ldg(bias + oc), bv1 = __ldg(bias + oc + 1);
        size_t o00 = base0 + (size_t)oc * 3136;
        size_t o10 = base1 + (size_t)oc * 3136;
#pragma unroll
        for (int p = 0; p < 4; ++p) {
            int i = p >> 1, j = p & 1;
            int off = i * 56 + j;
            out[o00 + off]        = acc[p][nt * 4 + 0] + bv0;
            out[o00 + 3136 + off] = acc[p][nt * 4 + 1] + bv1;
            out[o10 + off]        = acc[p][nt * 4 + 2] + bv0;
            out[o10 + 3136 + off] = acc[p][nt * 4 + 3] + bv1;
        }
    }
}

// ---------------------------------------------------------------------------
// Launcher (graph-capturable: kernel launches only)
// ---------------------------------------------------------------------------
extern "C" void kernel_launch(void* const* d_in, const int* in_sizes, int n_in,
                              void* d_out, int out_size) {
    const float* x    = (const float*)d_in[0];
    const float* W    = (const float*)d_in[1];
    const float* b    = (const float*)d_in[2];
    const float* rmsw = (const float*)d_in[3];
    float* out = (float*)d_out;

    wht_kernel<<<dim3(98, 32), 256>>>(x, rmsw);
    wino_in<<<6272, 256>>>();
    wino_wt<<<256, 256>>>(W);

    cudaFuncSetAttribute(wino_gemm, cudaFuncAttributeMaxDynamicSharedMemorySize,
                         WG_SMEM);
    wino_gemm<<<dim3(4, 392), 256, WG_SMEM>>>(b, out);
}